// round 4
// baseline (speedup 1.0000x reference)
#include <cuda_runtime.h>
#include <cuda_bf16.h>

// Fixed problem shape: B=2, S=2048, D=2048, W=4.
#define SEQ 2048
#define DIM 2048
#define NTHREADS 512           // DIM / 4 (float4 per thread)
#define EPSV 1e-6f

__global__ __launch_bounds__(NTHREADS, 2)
void gated_kernel(const float* __restrict__ x,
                  const float4* __restrict__ w4,     // weight as (D) float4 rows: w4[d] = {w[d][0..3]}
                  const float* __restrict__ alpha,   // (3,)
                  const float* __restrict__ rmsw,    // (D,)
                  float* __restrict__ out)
{
    const int s   = blockIdx.x;
    const int b   = blockIdx.y;
    const int tid = threadIdx.x;
    const int d   = tid * 4;

    const long rowBase = ((long)b * SEQ + s) * DIM;

    // Load x[s-k, d..d+3] for k=0..5 (zero-padded below sequence start)
    float4 X[6];
    X[0] = *(const float4*)(x + rowBase + d);
#pragma unroll
    for (int k = 1; k <= 5; k++) {
        if (s - k >= 0)
            X[k] = *(const float4*)(x + rowBase - (long)k * DIM + d);
        else
            X[k] = make_float4(0.f, 0.f, 0.f, 0.f);
    }

    // weight rows for the 4 owned d's: wq[j].{x,y,z,w} = w[d+j][0..3]
    float4 wq[4];
#pragma unroll
    for (int j = 0; j < 4; j++) wq[j] = __ldg(&w4[d + j]);

    // pre[k][j] = x[s-k, d+j] * x[s-k-2, d+j] * w[d+j][k]
    // partials: dots 1..3 and sum(pre^2) for k=0..3
    float p[4][4];
    float vals[7] = {0.f, 0.f, 0.f, 0.f, 0.f, 0.f, 0.f};

    const float X0a[4] = {X[0].x, X[0].y, X[0].z, X[0].w};
#pragma unroll
    for (int k = 0; k < 4; k++) {
        const float4 a = X[k];
        const float4 c = X[k + 2];
        const float aa[4] = {a.x, a.y, a.z, a.w};
        const float cc[4] = {c.x, c.y, c.z, c.w};
#pragma unroll
        for (int j = 0; j < 4; j++) {
            const float wkj = (k == 0) ? wq[j].x : (k == 1) ? wq[j].y : (k == 2) ? wq[j].z : wq[j].w;
            const float pv  = aa[j] * cc[j] * wkj;
            p[k][j] = pv;
            vals[3 + k] = fmaf(pv, pv, vals[3 + k]);
            if (k >= 1) vals[k - 1] = fmaf(X0a[j], aa[j], vals[k - 1]);
        }
    }

    // ---- block reduction of 7 values (16 warps) ----
    __shared__ float red[16][8];   // padded to 8 to avoid bank conflicts
    __shared__ float fin[8];
    const int lane = tid & 31;
    const int wid  = tid >> 5;

#pragma unroll
    for (int i = 0; i < 7; i++) {
        float v = vals[i];
#pragma unroll
        for (int o = 16; o > 0; o >>= 1) v += __shfl_down_sync(0xffffffffu, v, o);
        if (lane == 0) red[wid][i] = v;
    }
    __syncthreads();
    if (wid == 0) {
#pragma unroll
        for (int i = 0; i < 7; i++) {
            float v = (lane < 16) ? red[lane][i] : 0.f;
#pragma unroll
            for (int o = 8; o > 0; o >>= 1) v += __shfl_down_sync(0xffffffffu, v, o);
            if (lane == 0) fin[i] = v;
        }
    }
    __syncthreads();

    // scales: c_k = lam_k * rsqrt(var_k + eps); lam_0 = 1
    const float invD = 1.0f / (float)DIM;
    float cs[4];
    cs[0] = rsqrtf(fin[3] * invD + EPSV);
#pragma unroll
    for (int k = 1; k < 4; k++) {
        const float lam = tanhf(fin[k - 1] * __ldg(&alpha[k - 1]));
        cs[k] = lam * rsqrtf(fin[3 + k] * invD + EPSV);
    }

    // out[d+j] = x[s,d+j] + rms_w[d+j] * sum_k cs[k] * p[k][j] * w[d+j][k]
    const float4 rq = *(const float4*)(rmsw + d);
    const float rr[4] = {rq.x, rq.y, rq.z, rq.w};

    float4 o;
    float oo[4];
#pragma unroll
    for (int j = 0; j < 4; j++) {
        float acc = cs[0] * p[0][j] * wq[j].x;
        acc = fmaf(cs[1] * p[1][j], wq[j].y, acc);
        acc = fmaf(cs[2] * p[2][j], wq[j].z, acc);
        acc = fmaf(cs[3] * p[3][j], wq[j].w, acc);
        oo[j] = X0a[j] + rr[j] * acc;
    }
    o.x = oo[0]; o.y = oo[1]; o.z = oo[2]; o.w = oo[3];
    *(float4*)(out + rowBase + d) = o;
}

extern "C" void kernel_launch(void* const* d_in, const int* in_sizes, int n_in,
                              void* d_out, int out_size)
{
    const float* x     = (const float*)d_in[0];
    const float* w     = (const float*)d_in[1];
    const float* alpha = (const float*)d_in[2];
    const float* rmsw  = (const float*)d_in[3];
    float* out = (float*)d_out;

    const long total = (long)in_sizes[0];
    const int  B     = (int)(total / ((long)SEQ * DIM));   // = 2

    dim3 grid(SEQ, B);
    gated_kernel<<<grid, NTHREADS>>>(x, (const float4*)w, alpha, rmsw, out);
}

// round 5
// speedup vs baseline: 1.3861x; 1.3861x over previous
#include <cuda_runtime.h>
#include <cuda_bf16.h>

// Fixed problem shape: B=2, S=2048, D=2048, W=4.
#define SEQ 2048
#define DIM 2048
#define NT 512
#define TROWS 4          // seq rows per CTA (rolling register window)
#define EPSV 1e-6f

// Thread tid owns d_m = tid + 512*m for m=0..3  (all gmem accesses dense/coalesced)
__global__ __launch_bounds__(NT, 2)
void gated_kernel(const float* __restrict__ x,
                  const float4* __restrict__ w4,     // (D) float4: w4[d] = {w[d][0..3]}
                  const float* __restrict__ alpha,   // (3,)
                  const float* __restrict__ rmsw,    // (D,)
                  float* __restrict__ out)
{
    const int tile = blockIdx.x;
    const int b    = blockIdx.y;
    const int tid  = threadIdx.x;
    const int s0   = tile * TROWS;
    const int lane = tid & 31;
    const int wid  = tid >> 5;

    const float* xb = x   + ((long)b * SEQ) * DIM + tid;
    float*       ob = out + ((long)b * SEQ) * DIM + tid;

    // weights / rms weights for the 4 owned d's — fully coalesced
    float4 wq[4];
    float  rw[4];
#pragma unroll
    for (int m = 0; m < 4; m++) {
        wq[m] = __ldg(&w4[tid + 512 * m]);
        rw[m] = __ldg(&rmsw[tid + 512 * m]);
    }

    // Rolling window: Xw[slot][m], slot = (global row index within tile) % 6.
    // Row r (r=0..8) is seq row s0-5+r; at output t, x[s-k] lives in slot (5+t-k)%6.
    float Xw[6][4];
#pragma unroll
    for (int r = 0; r < 6; r++) {
        const int srow = s0 - 5 + r;
#pragma unroll
        for (int m = 0; m < 4; m++)
            Xw[r][m] = (srow >= 0) ? xb[(long)srow * DIM + 512 * m] : 0.f;
    }

    __shared__ float red[16][9];   // stride 9: conflict-free stage-2 reads
    __shared__ float csm[4];

#pragma unroll
    for (int t = 0; t < TROWS; t++) {
        if (t > 0) {
            const int slot = (5 + t) % 6;
#pragma unroll
            for (int m = 0; m < 4; m++)
                Xw[slot][m] = xb[(long)(s0 + t) * DIM + 512 * m];
        }

        // partial sums: dots(1..3) then sum(pre_k^2) for k=0..3
        float vals[7] = {0.f, 0.f, 0.f, 0.f, 0.f, 0.f, 0.f};
#pragma unroll
        for (int m = 0; m < 4; m++) {
            const float x0 = Xw[(5 + t) % 6][m];
            vals[0] = fmaf(x0, Xw[(4 + t) % 6][m], vals[0]);
            vals[1] = fmaf(x0, Xw[(3 + t) % 6][m], vals[1]);
            vals[2] = fmaf(x0, Xw[(2 + t) % 6][m], vals[2]);
            {
                const float pv = Xw[(5 + t) % 6][m] * Xw[(3 + t) % 6][m] * wq[m].x;
                vals[3] = fmaf(pv, pv, vals[3]);
            }
            {
                const float pv = Xw[(4 + t) % 6][m] * Xw[(2 + t) % 6][m] * wq[m].y;
                vals[4] = fmaf(pv, pv, vals[4]);
            }
            {
                const float pv = Xw[(3 + t) % 6][m] * Xw[(1 + t) % 6][m] * wq[m].z;
                vals[5] = fmaf(pv, pv, vals[5]);
            }
            {
                const float pv = Xw[(2 + t) % 6][m] * Xw[(t) % 6][m] * wq[m].w;
                vals[6] = fmaf(pv, pv, vals[6]);
            }
        }

        // ---- block reduce 7 values (stage 1: intra-warp) ----
#pragma unroll
        for (int i = 0; i < 7; i++) {
            float v = vals[i];
#pragma unroll
            for (int o = 16; o > 0; o >>= 1) v += __shfl_down_sync(0xffffffffu, v, o);
            if (lane == 0) red[wid][i] = v;
        }
        __syncthreads();

        // stage 2: warp 0 reduces 16 partials, lane 0 computes the 4 scales
        if (wid == 0) {
            float f[7];
#pragma unroll
            for (int i = 0; i < 7; i++) {
                float v = (lane < 16) ? red[lane][i] : 0.f;
#pragma unroll
                for (int o = 8; o > 0; o >>= 1) v += __shfl_down_sync(0xffffffffu, v, o);
                f[i] = v;
            }
            if (lane == 0) {
                const float invD = 1.0f / (float)DIM;
                csm[0] = rsqrtf(f[3] * invD + EPSV);
#pragma unroll
                for (int k = 1; k < 4; k++) {
                    const float lam = tanhf(f[k - 1] * __ldg(&alpha[k - 1]));
                    csm[k] = lam * rsqrtf(f[3 + k] * invD + EPSV);
                }
            }
        }
        __syncthreads();

        const float cs0 = csm[0], cs1 = csm[1], cs2 = csm[2], cs3 = csm[3];

        // recombine (pre recomputed from the register window) + store
#pragma unroll
        for (int m = 0; m < 4; m++) {
            const float x0 = Xw[(5 + t) % 6][m];
            const float pv0 = Xw[(5 + t) % 6][m] * Xw[(3 + t) % 6][m] * wq[m].x;
            const float pv1 = Xw[(4 + t) % 6][m] * Xw[(2 + t) % 6][m] * wq[m].y;
            const float pv2 = Xw[(3 + t) % 6][m] * Xw[(1 + t) % 6][m] * wq[m].z;
            const float pv3 = Xw[(2 + t) % 6][m] * Xw[(t) % 6][m]     * wq[m].w;
            float acc = cs0 * pv0 * wq[m].x;
            acc = fmaf(cs1 * pv1, wq[m].y, acc);
            acc = fmaf(cs2 * pv2, wq[m].z, acc);
            acc = fmaf(cs3 * pv3, wq[m].w, acc);
            ob[(long)(s0 + t) * DIM + 512 * m] = x0 + rw[m] * acc;
        }
        // csm(t+1) is only written by warp0 after the next __syncthreads(),
        // which every thread reaches only after reading csm(t) above — safe.
    }
}

extern "C" void kernel_launch(void* const* d_in, const int* in_sizes, int n_in,
                              void* d_out, int out_size)
{
    const float* x     = (const float*)d_in[0];
    const float* w     = (const float*)d_in[1];
    const float* alpha = (const float*)d_in[2];
    const float* rmsw  = (const float*)d_in[3];
    float* out = (float*)d_out;

    const long total = (long)in_sizes[0];
    const int  B     = (int)(total / ((long)SEQ * DIM));   // = 2

    dim3 grid(SEQ / TROWS, B);
    gated_kernel<<<grid, NT>>>(x, (const float4*)w, alpha, rmsw, out);
}

// round 7
// speedup vs baseline: 1.4152x; 1.0210x over previous
#include <cuda_runtime.h>
#include <cuda_bf16.h>

// Fixed problem shape: B=2, S=2048, D=2048, W=4.
#define SEQ   2048
#define DIM   2048
#define NT    512
#define TROWS 8
#define EPSV  1e-6f
#define D4    (DIM / 4)      // float4s per row = 512

__device__ __forceinline__ float warp_sum(float v) {
#pragma unroll
    for (int o = 16; o > 0; o >>= 1)
        v += __shfl_xor_sync(0xffffffffu, v, o);
    return v;
}

// Thread tid owns d = 4*tid .. 4*tid+3 (one float4 per row).
__global__ __launch_bounds__(NT, 2)
void gated_kernel(const float4* __restrict__ x4,
                  const float4* __restrict__ w4,     // w4[d] = {w[d][0..3]}
                  const float*  __restrict__ alpha,  // (3,)
                  const float4* __restrict__ rmsw4,  // (D/4,)
                  float4*       __restrict__ out4)
{
    const int tid  = threadIdx.x;
    const int s0   = blockIdx.x * TROWS;
    const int b    = blockIdx.y;
    const int lane = tid & 31;
    const int wid  = tid >> 5;

    const long base = ((long)b * SEQ) * D4 + tid;   // float4 index of (b, s=0, 4*tid)

    // per-thread weights: wq[j] = w[4*tid+j][0..3]  (strided, but once per CTA)
    float4 wq[4];
#pragma unroll
    for (int j = 0; j < 4; j++) wq[j] = __ldg(&w4[4 * tid + j]);
    const float4 rq = __ldg(&rmsw4[tid]);
    const float rr[4] = {rq.x, rq.y, rq.z, rq.w};
    const float wk[4][4] = {
        {wq[0].x, wq[0].y, wq[0].z, wq[0].w},
        {wq[1].x, wq[1].y, wq[1].z, wq[1].w},
        {wq[2].x, wq[2].y, wq[2].z, wq[2].w},
        {wq[3].x, wq[3].y, wq[3].z, wq[3].w}};

    // Rolling 6-row window. Row s lives in slot (s - s0 + 5) % 6.
    float Xw[6][4];
#pragma unroll
    for (int r = 0; r < 6; r++) {
        const int s = s0 - 5 + r;
        if (s >= 0) {
            const float4 v = x4[base + (long)s * D4];
            Xw[r][0] = v.x; Xw[r][1] = v.y; Xw[r][2] = v.z; Xw[r][3] = v.w;
        } else {
            Xw[r][0] = Xw[r][1] = Xw[r][2] = Xw[r][3] = 0.f;
        }
    }

    __shared__ float red[16][8];   // 16 warps x 7 values (pad 8)
    __shared__ float csm[4];

#pragma unroll
    for (int t = 0; t < TROWS; t++) {
        if (t > 0) {
            const int slot = (5 + t) % 6;
            const float4 v = x4[base + (long)(s0 + t) * D4];
            Xw[slot][0] = v.x; Xw[slot][1] = v.y; Xw[slot][2] = v.z; Xw[slot][3] = v.w;
        }
        const int s5 = (t + 5) % 6;   // x[s]
        const int s4 = (t + 4) % 6;   // x[s-1]
        const int s3 = (t + 3) % 6;   // x[s-2]
        const int s2 = (t + 2) % 6;   // x[s-3]
        const int s1 = (t + 1) % 6;   // x[s-4]
        const int sz = t % 6;         // x[s-5]

        // partials: dots k=1..3, then sum(pre_k^2) k=0..3
        float vals[7] = {0.f, 0.f, 0.f, 0.f, 0.f, 0.f, 0.f};
#pragma unroll
        for (int j = 0; j < 4; j++) {
            const float x0 = Xw[s5][j];
            vals[0] = fmaf(x0, Xw[s4][j], vals[0]);
            vals[1] = fmaf(x0, Xw[s3][j], vals[1]);
            vals[2] = fmaf(x0, Xw[s2][j], vals[2]);
            const float pv0 = Xw[s5][j] * Xw[s3][j] * wk[j][0];
            const float pv1 = Xw[s4][j] * Xw[s2][j] * wk[j][1];
            const float pv2 = Xw[s3][j] * Xw[s1][j] * wk[j][2];
            const float pv3 = Xw[s2][j] * Xw[sz][j] * wk[j][3];
            vals[3] = fmaf(pv0, pv0, vals[3]);
            vals[4] = fmaf(pv1, pv1, vals[4]);
            vals[5] = fmaf(pv2, pv2, vals[5]);
            vals[6] = fmaf(pv3, pv3, vals[6]);
        }

        // stage 1: butterfly warp sum, lane 0 publishes
#pragma unroll
        for (int i = 0; i < 7; i++) {
            const float v = warp_sum(vals[i]);
            if (lane == 0) red[wid][i] = v;
        }
        __syncthreads();

        // stage 2: warps 0..3 each produce one scale
        if (wid == 0) {
            float v = warp_sum((lane < 16) ? red[lane][3] : 0.f);
            if (lane == 0) csm[0] = rsqrtf(v * (1.0f / DIM) + EPSV);
        } else if (wid < 4) {
            const int k = wid;
            const float vd = warp_sum((lane < 16) ? red[lane][k - 1] : 0.f);
            const float vv = warp_sum((lane < 16) ? red[lane][3 + k] : 0.f);
            if (lane == 0) {
                const float lam = tanhf(vd * __ldg(&alpha[k - 1]));
                csm[k] = lam * rsqrtf(vv * (1.0f / DIM) + EPSV);
            }
        }
        __syncthreads();

        const float cs0 = csm[0], cs1 = csm[1], cs2 = csm[2], cs3 = csm[3];

        // recombine + store (pre recomputed from register window)
        float oo[4];
#pragma unroll
        for (int j = 0; j < 4; j++) {
            const float pv0 = Xw[s5][j] * Xw[s3][j] * wk[j][0];
            const float pv1 = Xw[s4][j] * Xw[s2][j] * wk[j][1];
            const float pv2 = Xw[s3][j] * Xw[s1][j] * wk[j][2];
            const float pv3 = Xw[s2][j] * Xw[sz][j] * wk[j][3];
            float acc = cs0 * pv0 * wk[j][0];
            acc = fmaf(cs1 * pv1, wk[j][1], acc);
            acc = fmaf(cs2 * pv2, wk[j][2], acc);
            acc = fmaf(cs3 * pv3, wk[j][3], acc);
            oo[j] = Xw[s5][j] + rr[j] * acc;
        }
        float4 o; o.x = oo[0]; o.y = oo[1]; o.z = oo[2]; o.w = oo[3];
        out4[base + (long)(s0 + t) * D4] = o;
        // csm(t+1) is rewritten only after the next __syncthreads(), which
        // follows every thread's read of csm(t) above — no extra barrier needed.
    }
}

extern "C" void kernel_launch(void* const* d_in, const int* in_sizes, int n_in,
                              void* d_out, int out_size)
{
    const float* x     = (const float*)d_in[0];
    const float* w     = (const float*)d_in[1];
    const float* alpha = (const float*)d_in[2];
    const float* rmsw  = (const float*)d_in[3];
    float* out = (float*)d_out;

    const long total = (long)in_sizes[0];
    const int  B     = (int)(total / ((long)SEQ * DIM));   // = 2

    dim3 grid(SEQ / TROWS, B);
    gated_kernel<<<grid, NT>>>((const float4*)x, (const float4*)w, alpha,
                               (const float4*)rmsw, (float4*)out);
}

// round 8
// speedup vs baseline: 1.4678x; 1.0372x over previous
#include <cuda_runtime.h>
#include <cuda_bf16.h>

// Fixed problem shape: B=2, S=2048, D=2048, W=4.
#define SEQ   2048
#define DIM   2048
#define NT    512
#define TROWS 8
#define EPSV  1e-6f
#define D4    (DIM / 4)      // float4s per row = 512

typedef unsigned long long u64;

// ---- packed f32x2 helpers (sm_103a FFMA2 path; only reachable via PTX) ----
static __device__ __forceinline__ u64 pk2(float lo, float hi) {
    u64 r; asm("mov.b64 %0, {%1, %2};" : "=l"(r) : "f"(lo), "f"(hi)); return r;
}
static __device__ __forceinline__ void up2(u64 v, float& lo, float& hi) {
    asm("mov.b64 {%0, %1}, %2;" : "=f"(lo), "=f"(hi) : "l"(v));
}
static __device__ __forceinline__ u64 mul2(u64 a, u64 b) {
    u64 r; asm("mul.rn.f32x2 %0, %1, %2;" : "=l"(r) : "l"(a), "l"(b)); return r;
}
static __device__ __forceinline__ u64 fma2(u64 a, u64 b, u64 c) {
    u64 r; asm("fma.rn.f32x2 %0, %1, %2, %3;" : "=l"(r) : "l"(a), "l"(b), "l"(c)); return r;
}

static __device__ __forceinline__ float warp_sum(float v) {
#pragma unroll
    for (int o = 16; o > 0; o >>= 1)
        v += __shfl_xor_sync(0xffffffffu, v, o);
    return v;
}

// Thread tid owns d = 4*tid .. 4*tid+3, held as two f32x2 pairs.
__global__ __launch_bounds__(NT, 2)
void gated_kernel(const float4* __restrict__ x4,
                  const float4* __restrict__ w4,     // w4[d] = {w[d][0..3]}
                  const float*  __restrict__ alpha,  // (3,)
                  const float4* __restrict__ rmsw4,  // (D/4,)
                  float4*       __restrict__ out4)
{
    const int tid  = threadIdx.x;
    const int s0   = blockIdx.x * TROWS;
    const int b    = blockIdx.y;
    const int lane = tid & 31;
    const int wid  = tid >> 5;

    const long base = ((long)b * SEQ) * D4 + tid;   // float4 index of (b, s=0, 4*tid)

    // W2[k] = w[d][k]^2, packed as pairs (j0,j1),(j2,j3).
    // (pre^2 = (x1 x2)^2 w^2 and contrib = (x1 x2) w^2, so only w^2 is needed.)
    float4 wq[4];
#pragma unroll
    for (int j = 0; j < 4; j++) wq[j] = __ldg(&w4[4 * tid + j]);
    u64 W2p[4][2];
    {
        const float wkj[4][4] = {
            {wq[0].x, wq[1].x, wq[2].x, wq[3].x},   // k=0 over j=0..3
            {wq[0].y, wq[1].y, wq[2].y, wq[3].y},
            {wq[0].z, wq[1].z, wq[2].z, wq[3].z},
            {wq[0].w, wq[1].w, wq[2].w, wq[3].w}};
#pragma unroll
        for (int k = 0; k < 4; k++) {
            W2p[k][0] = pk2(wkj[k][0] * wkj[k][0], wkj[k][1] * wkj[k][1]);
            W2p[k][1] = pk2(wkj[k][2] * wkj[k][2], wkj[k][3] * wkj[k][3]);
        }
    }
    const float4 rq = __ldg(&rmsw4[tid]);
    const u64 rp[2] = {pk2(rq.x, rq.y), pk2(rq.z, rq.w)};

    // Rolling 7-row window (2 output rows per iteration).
    // Row s lives in slot (s - s0 + 5) % 7.
    u64 Xp[7][2];
#pragma unroll
    for (int r = 0; r < 7; r++) {
        const int s = s0 - 5 + r;
        if (s >= 0) {
            const float4 v = x4[base + (long)s * D4];
            Xp[r][0] = pk2(v.x, v.y);
            Xp[r][1] = pk2(v.z, v.w);
        } else {
            Xp[r][0] = 0ull; Xp[r][1] = 0ull;
        }
    }

    __shared__ float red[16][16];  // 16 warps x 14 values (pad 16)
    __shared__ float csm[8];       // scales for the 2 rows

#pragma unroll
    for (int t = 0; t < TROWS; t += 2) {
        if (t > 0) {
            {
                const float4 v = x4[base + (long)(s0 + t) * D4];
                const int sl = (t + 5) % 7;
                Xp[sl][0] = pk2(v.x, v.y); Xp[sl][1] = pk2(v.z, v.w);
            }
            {
                const float4 v = x4[base + (long)(s0 + t + 1) * D4];
                const int sl = (t + 6) % 7;
                Xp[sl][0] = pk2(v.x, v.y); Xp[sl][1] = pk2(v.z, v.w);
            }
        }

        // ---- stage 1: per-row partials, warp reduce, publish ----
#pragma unroll
        for (int r = 0; r < 2; r++) {
            const int rt = t + r;
            const int a0 = (rt + 5) % 7, a1 = (rt + 4) % 7, a2 = (rt + 3) % 7;
            const int a3 = (rt + 2) % 7, a4 = (rt + 1) % 7, a5 = rt % 7;

            u64 vd[3] = {0ull, 0ull, 0ull};
            u64 vv[4] = {0ull, 0ull, 0ull, 0ull};
#pragma unroll
            for (int p = 0; p < 2; p++) {
                const u64 x0 = Xp[a0][p], x1 = Xp[a1][p], x2 = Xp[a2][p];
                const u64 x3 = Xp[a3][p], x4v = Xp[a4][p], x5 = Xp[a5][p];
                vd[0] = fma2(x0, x1, vd[0]);
                vd[1] = fma2(x0, x2, vd[1]);
                vd[2] = fma2(x0, x3, vd[2]);
                const u64 q0 = mul2(x0, x2);
                const u64 q1 = mul2(x1, x3);
                const u64 q2 = mul2(x2, x4v);
                const u64 q3 = mul2(x3, x5);
                vv[0] = fma2(mul2(q0, q0), W2p[0][p], vv[0]);
                vv[1] = fma2(mul2(q1, q1), W2p[1][p], vv[1]);
                vv[2] = fma2(mul2(q2, q2), W2p[2][p], vv[2]);
                vv[3] = fma2(mul2(q3, q3), W2p[3][p], vv[3]);
            }
            float lo, hi;
#pragma unroll
            for (int i = 0; i < 3; i++) {
                up2(vd[i], lo, hi);
                const float v = warp_sum(lo + hi);
                if (lane == 0) red[wid][r * 7 + i] = v;
            }
#pragma unroll
            for (int k = 0; k < 4; k++) {
                up2(vv[k], lo, hi);
                const float v = warp_sum(lo + hi);
                if (lane == 0) red[wid][r * 7 + 3 + k] = v;
            }
        }
        __syncthreads();

        // ---- stage 2: 8 warps, one (row, k) scale each ----
        if (wid < 8) {
            const int row = wid >> 2, k = wid & 3;
            if (k == 0) {
                const float v = warp_sum((lane < 16) ? red[lane][row * 7 + 3] : 0.f);
                if (lane == 0) csm[row * 4] = rsqrtf(v * (1.0f / DIM) + EPSV);
            } else {
                const float vd_ = warp_sum((lane < 16) ? red[lane][row * 7 + k - 1] : 0.f);
                const float vv_ = warp_sum((lane < 16) ? red[lane][row * 7 + 3 + k] : 0.f);
                if (lane == 0) {
                    const float lam = tanhf(vd_ * __ldg(&alpha[k - 1]));
                    csm[row * 4 + k] = lam * rsqrtf(vv_ * (1.0f / DIM) + EPSV);
                }
            }
        }
        __syncthreads();

        // ---- recombine + store both rows ----
#pragma unroll
        for (int r = 0; r < 2; r++) {
            const int rt = t + r;
            const int a0 = (rt + 5) % 7, a1 = (rt + 4) % 7, a2 = (rt + 3) % 7;
            const int a3 = (rt + 2) % 7, a4 = (rt + 1) % 7, a5 = rt % 7;
            u64 cp[4];
#pragma unroll
            for (int k = 0; k < 4; k++) {
                const float c = csm[r * 4 + k];
                cp[k] = pk2(c, c);
            }
            float oo[4];
#pragma unroll
            for (int p = 0; p < 2; p++) {
                const u64 x0 = Xp[a0][p];
                const u64 q0 = mul2(x0, Xp[a2][p]);
                const u64 q1 = mul2(Xp[a1][p], Xp[a3][p]);
                const u64 q2 = mul2(Xp[a2][p], Xp[a4][p]);
                const u64 q3 = mul2(Xp[a3][p], Xp[a5][p]);
                u64 acc = mul2(cp[0], mul2(q0, W2p[0][p]));
                acc = fma2(cp[1], mul2(q1, W2p[1][p]), acc);
                acc = fma2(cp[2], mul2(q2, W2p[2][p]), acc);
                acc = fma2(cp[3], mul2(q3, W2p[3][p]), acc);
                const u64 o = fma2(rp[p], acc, x0);   // x0 + rms * acc
                up2(o, oo[2 * p], oo[2 * p + 1]);
            }
            float4 ov; ov.x = oo[0]; ov.y = oo[1]; ov.z = oo[2]; ov.w = oo[3];
            out4[base + (long)(s0 + rt) * D4] = ov;
        }
        // red is rewritten only before the next barrier-1; csm only after it — safe.
    }
}

extern "C" void kernel_launch(void* const* d_in, const int* in_sizes, int n_in,
                              void* d_out, int out_size)
{
    const float* x     = (const float*)d_in[0];
    const float* w     = (const float*)d_in[1];
    const float* alpha = (const float*)d_in[2];
    const float* rmsw  = (const float*)d_in[3];
    float* out = (float*)d_out;

    const long total = (long)in_sizes[0];
    const int  B     = (int)(total / ((long)SEQ * DIM));   // = 2

    dim3 grid(SEQ / TROWS, B);
    gated_kernel<<<grid, NT>>>((const float4*)x, (const float4*)w, alpha,
                               (const float4*)rmsw, (float4*)out);
}